// round 3
// baseline (speedup 1.0000x reference)
#include <cuda_runtime.h>

#define NBLK 148
#define NTHR 1024
#define NWARP (NBLK*32)     // 4736 warps chip-wide

#define Bn 4
#define Cn 256
#define ICn 128
#define Sn 64
#define NTOK (Bn*Sn)        // 256
#define REGION 1024
#define EPSf 1e-5f

// Scratch (allocation-free __device__ globals)
__device__ float d_P   [NTOK*Cn];
__device__ float d_g   [NTOK*ICn];
__device__ float d_th  [NTOK*ICn];
__device__ float d_ph  [NTOK*ICn];
__device__ float d_attn[Bn*Sn*Sn];
__device__ float d_y   [NTOK*ICn];
__device__ float d_val [Bn*Cn*Sn];

// grid barrier state (count resets each barrier; gen grows monotonically,
// persists correctly across graph replays)
__device__ unsigned g_cnt = 0;
__device__ unsigned g_gen = 0;

__device__ __forceinline__ void grid_sync() {
    __syncthreads();
    if (threadIdx.x == 0) {
        unsigned gen = *(volatile unsigned*)&g_gen;
        __threadfence();
        if (atomicAdd(&g_cnt, 1) == NBLK - 1) {
            g_cnt = 0;
            __threadfence();
            *(volatile unsigned*)&g_gen = gen + 1;
        } else {
            while (*(volatile unsigned*)&g_gen == gen) { }
        }
        __threadfence();
    }
    __syncthreads();
}

__global__ void __launch_bounds__(NTHR, 1) fused_kernel(
    const float* __restrict__ x,
    const float* __restrict__ g_w,  const float* __restrict__ g_b,
    const float* __restrict__ th_w, const float* __restrict__ th_b,
    const float* __restrict__ ph_w, const float* __restrict__ ph_b,
    const float* __restrict__ W_w,  const float* __restrict__ W_b,
    const float* __restrict__ gamma,const float* __restrict__ beta,
    const float* __restrict__ mean, const float* __restrict__ var,
    float* __restrict__ z)
{
    int tid  = threadIdx.x;
    int lane = tid & 31;
    int wid  = tid >> 5;
    int gw   = blockIdx.x * 32 + wid;          // global warp id
    int gt   = blockIdx.x * NTHR + tid;        // global thread id

    // ---------------- Phase A: stripe mean pool ----------------
    // region r = (b*Cn + c)*Sn + s : 1024 contiguous floats
    for (int r = gw; r < NTOK * Cn; r += NWARP) {
        const float4* p = (const float4*)(x + (size_t)r * REGION);
        float sum = 0.f;
#pragma unroll
        for (int i = 0; i < 8; i++) {
            float4 v = p[lane + i * 32];
            sum += (v.x + v.y) + (v.z + v.w);
        }
#pragma unroll
        for (int o = 16; o; o >>= 1) sum += __shfl_down_sync(0xffffffffu, sum, o);
        if (lane == 0) {
            int b = r >> 14;                 // / (Cn*Sn)
            int rem = r & 16383;
            int c = rem >> 6, s = rem & 63;
            d_P[(b * Sn + s) * Cn + c] = sum * (1.0f / REGION);
        }
    }
    grid_sync();

    // ---------------- Phase B: g/theta/phi projections ----------------
    // warp tile: 4 tokens x 8 outputs; 64 token-tiles x 48 out-tiles = 3072 warps
    if (gw < 3072) {
        int tt = gw & 63;                    // token tile
        int jt = gw >> 6;                    // out tile 0..47  (o0 = jt*8 in [0,384))
        int tok0 = tt * 4;
        int o0 = jt * 8;
        int m = o0 >> 7;                     // 0:g 1:th 2:ph
        int i0 = o0 & 127;
        const float* wsrc = (m == 0) ? g_w : (m == 1) ? th_w : ph_w;
        const float* bsrc = (m == 0) ? g_b : (m == 1) ? th_b : ph_b;
        float*       osrc = (m == 0) ? d_g : (m == 1) ? d_th : d_ph;

        float acc[4][8];
#pragma unroll
        for (int t = 0; t < 4; t++)
#pragma unroll
            for (int j = 0; j < 8; j++) acc[t][j] = 0.f;

#pragma unroll
        for (int kk = 0; kk < 8; kk++) {
            int c = kk * 32 + lane;
            float pv[4], wv[8];
#pragma unroll
            for (int t = 0; t < 4; t++) pv[t] = d_P[(tok0 + t) * Cn + c];
#pragma unroll
            for (int j = 0; j < 8; j++) wv[j] = wsrc[(i0 + j) * Cn + c];
#pragma unroll
            for (int t = 0; t < 4; t++)
#pragma unroll
                for (int j = 0; j < 8; j++)
                    acc[t][j] = fmaf(pv[t], wv[j], acc[t][j]);
        }
#pragma unroll
        for (int t = 0; t < 4; t++)
#pragma unroll
            for (int j = 0; j < 8; j++)
#pragma unroll
                for (int o = 16; o; o >>= 1)
                    acc[t][j] += __shfl_xor_sync(0xffffffffu, acc[t][j], o);

        int mt = lane >> 3, mj = lane & 7;
        float outv = 0.f;
#pragma unroll
        for (int t = 0; t < 4; t++)
#pragma unroll
            for (int j = 0; j < 8; j++)
                if (t == mt && j == mj) outv = acc[t][j];
        outv += bsrc[i0 + mj];
        osrc[(tok0 + mt) * ICn + i0 + mj] = outv;
    }
    grid_sync();

    // ---------------- Phase C1: f = theta @ phi^T ----------------
    // 16384 dots of length 128; warp per dot
    for (int o = gw; o < Bn * Sn * Sn; o += NWARP) {
        int b = o >> 12;
        int s = (o >> 6) & 63;
        int r = o & 63;
        float4 a = ((const float4*)(d_th + (b * Sn + s) * ICn))[lane];
        float4 c4 = ((const float4*)(d_ph + (b * Sn + r) * ICn))[lane];
        float p = a.x * c4.x + a.y * c4.y + a.z * c4.z + a.w * c4.w;
#pragma unroll
        for (int oo = 16; oo; oo >>= 1) p += __shfl_down_sync(0xffffffffu, p, oo);
        if (lane == 0) d_attn[o] = p;
    }
    grid_sync();

    // ---------------- Phase C2: row softmax (in place) ----------------
    if (gw < NTOK) {
        float* row = d_attn + gw * Sn;
        float v0 = row[lane], v1 = row[lane + 32];
        float mx = fmaxf(v0, v1);
#pragma unroll
        for (int o = 16; o; o >>= 1) mx = fmaxf(mx, __shfl_xor_sync(0xffffffffu, mx, o));
        float e0 = __expf(v0 - mx), e1 = __expf(v1 - mx);
        float sum = e0 + e1;
#pragma unroll
        for (int o = 16; o; o >>= 1) sum += __shfl_xor_sync(0xffffffffu, sum, o);
        float inv = 1.0f / sum;
        row[lane]      = e0 * inv;
        row[lane + 32] = e1 * inv;
    }
    grid_sync();

    // ---------------- Phase D1: y = attn @ g ----------------
    // 32768 outputs; thread per output (bs, i)
    if (gt < NTOK * ICn) {
        int bs = gt >> 7;
        int i  = gt & 127;
        int b  = bs >> 6;
        const float* arow = d_attn + bs * Sn;
        const float* gb   = d_g + (b * Sn) * ICn + i;
        float acc = 0.f;
#pragma unroll 8
        for (int r = 0; r < Sn; r++) acc = fmaf(arow[r], gb[r * ICn], acc);
        d_y[bs * ICn + i] = acc;
    }
    grid_sync();

    // ---------------- Phase D2: val = BN(W @ y + W_b) ----------------
    // 65536 outputs; thread per output t = (b*Cn + c)*Sn + s
    if (gt < Bn * Cn * Sn) {
        int bc = gt >> 6;
        int s  = gt & 63;
        int b  = bc >> 8;
        int c  = bc & 255;
        const float* w  = W_w + c * ICn;
        const float* yb = d_y + (b * Sn + s) * ICn;
        float acc = 0.f;
#pragma unroll 8
        for (int i = 0; i < ICn; i++) acc = fmaf(w[i], yb[i], acc);
        float inv = gamma[c] * rsqrtf(var[c] + EPSf);
        d_val[gt] = (acc + W_b[c] - mean[c]) * inv + beta[c];
    }
    grid_sync();

    // ---------------- Phase E: broadcast + residual ----------------
    const int total4 = Bn * Cn * Sn * (REGION / 4);   // 16,777,216 float4
    for (int idx = gt; idx < total4; idx += NBLK * NTHR) {
        float v = d_val[idx >> 8];
        float4 a = ((const float4*)x)[idx];
        a.x += v; a.y += v; a.z += v; a.w += v;
        ((float4*)z)[idx] = a;
    }
}

extern "C" void kernel_launch(void* const* d_in, const int* in_sizes, int n_in,
                              void* d_out, int out_size) {
    const float* x      = (const float*)d_in[0];
    const float* g_w    = (const float*)d_in[1];
    const float* g_b    = (const float*)d_in[2];
    const float* th_w   = (const float*)d_in[3];
    const float* th_b   = (const float*)d_in[4];
    const float* ph_w   = (const float*)d_in[5];
    const float* ph_b   = (const float*)d_in[6];
    const float* W_w    = (const float*)d_in[7];
    const float* W_b    = (const float*)d_in[8];
    const float* gamma  = (const float*)d_in[9];
    const float* beta   = (const float*)d_in[10];
    const float* mean   = (const float*)d_in[11];
    const float* var    = (const float*)d_in[12];
    float* z = (float*)d_out;

    fused_kernel<<<NBLK, NTHR>>>(x, g_w, g_b, th_w, th_b, ph_w, ph_b,
                                 W_w, W_b, gamma, beta, mean, var, z);
}

// round 4
// speedup vs baseline: 1.4500x; 1.4500x over previous
#include <cuda_runtime.h>

#define Bn 4
#define Cn 256
#define ICn 128
#define Sn 64
#define NTOK (Bn*Sn)        // 256
#define REGION 1024
#define EPSf 1e-5f

// Scratch (allocation-free __device__ globals)
__device__ float d_P  [NTOK*Cn];      // pooled tokens [tok][c]
__device__ float d_g  [NTOK*ICn];
__device__ float d_th [NTOK*ICn];
__device__ float d_ph [NTOK*ICn];
__device__ float d_y  [NTOK*ICn];
__device__ float d_val[Bn*Cn*Sn];     // BN-folded broadcast values [b][c][s]

// ---------------------------------------------------------------------------
// K1: stripe mean pool. One warp per 1024-float contiguous region.
// region r = (b*Cn+c)*Sn + s  ->  P[(b*Sn+s)*Cn + c]
// ---------------------------------------------------------------------------
__global__ void pool_kernel(const float* __restrict__ x) {
    int warp = (blockIdx.x * blockDim.x + threadIdx.x) >> 5;   // 0..65535
    int lane = threadIdx.x & 31;
    const float4* p = (const float4*)(x + (size_t)warp * REGION);
    float sum = 0.f;
#pragma unroll
    for (int i = 0; i < 8; i++) {
        float4 v = p[lane + i * 32];
        sum += (v.x + v.y) + (v.z + v.w);
    }
#pragma unroll
    for (int o = 16; o; o >>= 1) sum += __shfl_down_sync(0xffffffffu, sum, o);
    if (lane == 0) {
        int b   = warp >> 14;
        int rem = warp & 16383;
        int c   = rem >> 6;
        int s   = rem & 63;
        d_P[(b * Sn + s) * Cn + c] = sum * (1.0f / REGION);
    }
}

// ---------------------------------------------------------------------------
// K2: g/theta/phi projections as one tiled GEMM (32x32 tiles, 96 blocks).
// ---------------------------------------------------------------------------
__global__ void proj_kernel(const float* __restrict__ g_w,  const float* __restrict__ g_b,
                            const float* __restrict__ th_w, const float* __restrict__ th_b,
                            const float* __restrict__ ph_w, const float* __restrict__ ph_b) {
    __shared__ float As[32][33];
    __shared__ float Bs[32][33];
    int t0 = blockIdx.x * 32;
    int oT = blockIdx.y;                 // 0..11
    int mat  = oT >> 2;
    int row0 = (oT & 3) * 32;
    const float* wsrc = (mat == 0) ? g_w : (mat == 1) ? th_w : ph_w;
    const float* bsrc = (mat == 0) ? g_b : (mat == 1) ? th_b : ph_b;
    float*       osrc = (mat == 0) ? d_g : (mat == 1) ? d_th : d_ph;

    int tid = threadIdx.x;
    int tx = tid & 15, ty = tid >> 4;
    float acc[2][2] = {{0.f,0.f},{0.f,0.f}};

    for (int k0 = 0; k0 < Cn; k0 += 32) {
#pragma unroll
        for (int l = 0; l < 4; l++) {
            int idx = tid + l * 256;
            int r = idx >> 5, k = idx & 31;
            As[r][k] = d_P[(t0 + r) * Cn + k0 + k];
            Bs[r][k] = wsrc[(row0 + r) * Cn + k0 + k];
        }
        __syncthreads();
#pragma unroll
        for (int k = 0; k < 32; k++) {
            float a0 = As[ty * 2][k], a1 = As[ty * 2 + 1][k];
            float b0 = Bs[tx * 2][k], b1 = Bs[tx * 2 + 1][k];
            acc[0][0] = fmaf(a0, b0, acc[0][0]);
            acc[0][1] = fmaf(a0, b1, acc[0][1]);
            acc[1][0] = fmaf(a1, b0, acc[1][0]);
            acc[1][1] = fmaf(a1, b1, acc[1][1]);
        }
        __syncthreads();
    }
#pragma unroll
    for (int di = 0; di < 2; di++)
#pragma unroll
        for (int dj = 0; dj < 2; dj++) {
            int tok = t0 + ty * 2 + di;
            int i   = row0 + tx * 2 + dj;
            osrc[tok * ICn + i] = acc[di][dj] + bsrc[i];
        }
}

// ---------------------------------------------------------------------------
// K3: fused attention row: f = th[s]·ph^T, softmax, y[s] = attn·g.
// One block per (b,s) token row: 256 blocks, 256 threads.
// ---------------------------------------------------------------------------
__global__ void attn_kernel() {
    __shared__ float th_s[ICn];          // theta row
    __shared__ float at_s[Sn];           // f row -> attn row
    int bs = blockIdx.x;                 // b*Sn + s
    int b  = bs >> 6;
    int tid = threadIdx.x;
    int warp = tid >> 5, lane = tid & 31;

    if (tid < ICn) th_s[tid] = d_th[bs * ICn + tid];
    __syncthreads();

    // f[r] for r = warp*8 .. warp*8+7 (8 warps x 8 dots)
    const float4* th4 = (const float4*)th_s;
    float4 a = th4[lane];                // lane < 32 covers all 128 floats
#pragma unroll
    for (int d = 0; d < 8; d++) {
        int r = warp * 8 + d;
        float4 p = ((const float4*)(d_ph + (b * Sn + r) * ICn))[lane];
        float acc = a.x * p.x + a.y * p.y + a.z * p.z + a.w * p.w;
#pragma unroll
        for (int o = 16; o; o >>= 1) acc += __shfl_down_sync(0xffffffffu, acc, o);
        if (lane == 0) at_s[r] = acc;
    }
    __syncthreads();

    // softmax over 64 entries by warp 0
    if (warp == 0) {
        float v0 = at_s[lane], v1 = at_s[lane + 32];
        float m = fmaxf(v0, v1);
#pragma unroll
        for (int o = 16; o; o >>= 1) m = fmaxf(m, __shfl_xor_sync(0xffffffffu, m, o));
        float e0 = __expf(v0 - m), e1 = __expf(v1 - m);
        float sum = e0 + e1;
#pragma unroll
        for (int o = 16; o; o >>= 1) sum += __shfl_xor_sync(0xffffffffu, sum, o);
        float inv = 1.0f / sum;
        at_s[lane]      = e0 * inv;
        at_s[lane + 32] = e1 * inv;
    }
    __syncthreads();

    // y[s][i] = sum_r attn[r] * g[r][i] ; threads 0..127 each own an i
    if (tid < ICn) {
        const float* gb = d_g + b * Sn * ICn + tid;
        float acc = 0.f;
#pragma unroll 16
        for (int r = 0; r < Sn; r++) acc = fmaf(at_s[r], gb[r * ICn], acc);
        d_y[bs * ICn + tid] = acc;
    }
}

// ---------------------------------------------------------------------------
// K4: output projection + folded BatchNorm.
// grid = 4 b x 16 c-chunks = 64 blocks, 256 threads. y staged transposed.
// ---------------------------------------------------------------------------
__global__ void wproj_kernel(const float* __restrict__ W_w,   const float* __restrict__ W_b,
                             const float* __restrict__ gamma, const float* __restrict__ beta,
                             const float* __restrict__ mean,  const float* __restrict__ var) {
    __shared__ float y_t[ICn * 65];
    __shared__ float Ws[16 * ICn];
    int b  = blockIdx.x >> 4;
    int c0 = (blockIdx.x & 15) * 16;
    int tid = threadIdx.x;
    const float* y = d_y + b * Sn * ICn;

    for (int idx = tid; idx < Sn * ICn; idx += 256) {
        int s = idx >> 7, i = idx & 127;
        y_t[i * 65 + s] = y[idx];
    }
    for (int idx = tid; idx < 16 * ICn; idx += 256)
        Ws[idx] = W_w[c0 * ICn + idx];
    __syncthreads();

    int s = tid & 63;
    int cl0 = tid >> 6;
#pragma unroll
    for (int pass = 0; pass < 4; pass++) {
        int cl = pass * 4 + cl0;
        int c  = c0 + cl;
        const float* w = Ws + cl * ICn;
        float acc = 0.f;
#pragma unroll 16
        for (int i = 0; i < ICn; i++) acc = fmaf(w[i], y_t[i * 65 + s], acc);
        float inv = gamma[c] * rsqrtf(var[c] + EPSf);
        d_val[(b * Cn + c) * Sn + s] = (acc + W_b[c] - mean[c]) * inv + beta[c];
    }
}

// ---------------------------------------------------------------------------
// K5: broadcast + residual. Pure float4 stream.
// ---------------------------------------------------------------------------
__global__ void residual_kernel(const float* __restrict__ x, float* __restrict__ z) {
    int idx = blockIdx.x * blockDim.x + threadIdx.x;
    float v = d_val[idx >> 8];
    float4 a = ((const float4*)x)[idx];
    a.x += v; a.y += v; a.z += v; a.w += v;
    ((float4*)z)[idx] = a;
}

// ---------------------------------------------------------------------------
extern "C" void kernel_launch(void* const* d_in, const int* in_sizes, int n_in,
                              void* d_out, int out_size) {
    const float* x      = (const float*)d_in[0];
    const float* g_w    = (const float*)d_in[1];
    const float* g_b    = (const float*)d_in[2];
    const float* th_w   = (const float*)d_in[3];
    const float* th_b   = (const float*)d_in[4];
    const float* ph_w   = (const float*)d_in[5];
    const float* ph_b   = (const float*)d_in[6];
    const float* W_w    = (const float*)d_in[7];
    const float* W_b    = (const float*)d_in[8];
    const float* gamma  = (const float*)d_in[9];
    const float* beta   = (const float*)d_in[10];
    const float* mean   = (const float*)d_in[11];
    const float* var    = (const float*)d_in[12];
    float* z = (float*)d_out;

    pool_kernel<<<8192, 256>>>(x);
    dim3 pg(NTOK / 32, 12);
    proj_kernel<<<pg, 256>>>(g_w, g_b, th_w, th_b, ph_w, ph_b);
    attn_kernel<<<NTOK, 256>>>();
    wproj_kernel<<<64, 256>>>(W_w, W_b, gamma, beta, mean, var);
    residual_kernel<<<(Bn * Cn * Sn * (REGION / 4)) / 256, 256>>>(x, z);
}

// round 5
// speedup vs baseline: 1.4696x; 1.0135x over previous
#include <cuda_runtime.h>

#define Bn 4
#define Cn 256
#define ICn 128
#define Sn 64
#define NTOK (Bn*Sn)        // 256
#define REGION 1024
#define EPSf 1e-5f

// Scratch (allocation-free __device__ globals)
__device__ float d_P  [NTOK*Cn];      // pooled tokens [tok][c]
__device__ float d_g  [NTOK*ICn];
__device__ float d_th [NTOK*ICn];
__device__ float d_ph [NTOK*ICn];
__device__ float d_yT [Bn*ICn*Sn];    // y TRANSPOSED: [b][i][s]
__device__ float d_val[Bn*Cn*Sn];     // BN-folded broadcast values [b][c][s]

// ---------------------------------------------------------------------------
// K1: stripe mean pool. One warp per 1024-float contiguous region.
// region r = (b*Cn+c)*Sn + s  ->  P[(b*Sn+s)*Cn + c]
// ---------------------------------------------------------------------------
__global__ void pool_kernel(const float* __restrict__ x) {
    int warp = (blockIdx.x * blockDim.x + threadIdx.x) >> 5;   // 0..65535
    int lane = threadIdx.x & 31;
    const float4* p = (const float4*)(x + (size_t)warp * REGION);
    float sum = 0.f;
#pragma unroll
    for (int i = 0; i < 8; i++) {
        float4 v = p[lane + i * 32];
        sum += (v.x + v.y) + (v.z + v.w);
    }
#pragma unroll
    for (int o = 16; o; o >>= 1) sum += __shfl_down_sync(0xffffffffu, sum, o);
    if (lane == 0) {
        int b   = warp >> 14;
        int rem = warp & 16383;
        int c   = rem >> 6;
        int s   = rem & 63;
        d_P[(b * Sn + s) * Cn + c] = sum * (1.0f / REGION);
    }
}

// ---------------------------------------------------------------------------
// K2: g/theta/phi projections as one tiled GEMM (32x32 tiles, 96 blocks).
// ---------------------------------------------------------------------------
__global__ void proj_kernel(const float* __restrict__ g_w,  const float* __restrict__ g_b,
                            const float* __restrict__ th_w, const float* __restrict__ th_b,
                            const float* __restrict__ ph_w, const float* __restrict__ ph_b) {
    __shared__ float As[32][33];
    __shared__ float Bs[32][33];
    int t0 = blockIdx.x * 32;
    int oT = blockIdx.y;                 // 0..11
    int mat  = oT >> 2;
    int row0 = (oT & 3) * 32;
    const float* wsrc = (mat == 0) ? g_w : (mat == 1) ? th_w : ph_w;
    const float* bsrc = (mat == 0) ? g_b : (mat == 1) ? th_b : ph_b;
    float*       osrc = (mat == 0) ? d_g : (mat == 1) ? d_th : d_ph;

    int tid = threadIdx.x;
    int tx = tid & 15, ty = tid >> 4;
    float acc[2][2] = {{0.f,0.f},{0.f,0.f}};

    for (int k0 = 0; k0 < Cn; k0 += 32) {
#pragma unroll
        for (int l = 0; l < 4; l++) {
            int idx = tid + l * 256;
            int r = idx >> 5, k = idx & 31;
            As[r][k] = d_P[(t0 + r) * Cn + k0 + k];
            Bs[r][k] = wsrc[(row0 + r) * Cn + k0 + k];
        }
        __syncthreads();
#pragma unroll
        for (int k = 0; k < 32; k++) {
            float a0 = As[ty * 2][k], a1 = As[ty * 2 + 1][k];
            float b0 = Bs[tx * 2][k], b1 = Bs[tx * 2 + 1][k];
            acc[0][0] = fmaf(a0, b0, acc[0][0]);
            acc[0][1] = fmaf(a0, b1, acc[0][1]);
            acc[1][0] = fmaf(a1, b0, acc[1][0]);
            acc[1][1] = fmaf(a1, b1, acc[1][1]);
        }
        __syncthreads();
    }
#pragma unroll
    for (int di = 0; di < 2; di++)
#pragma unroll
        for (int dj = 0; dj < 2; dj++) {
            int tok = t0 + ty * 2 + di;
            int i   = row0 + tx * 2 + dj;
            osrc[tok * ICn + i] = acc[di][dj] + bsrc[i];
        }
}

// ---------------------------------------------------------------------------
// K3: fused attention row: f = th[s]·ph^T, softmax, y[s] = attn·g.
// One block per (b,s) token row: 256 blocks, 256 threads.
// Writes y TRANSPOSED: d_yT[(b*ICn + i)*Sn + s].
// ---------------------------------------------------------------------------
__global__ void attn_kernel() {
    __shared__ float th_s[ICn];          // theta row
    __shared__ float at_s[Sn];           // f row -> attn row
    int bs = blockIdx.x;                 // b*Sn + s
    int b  = bs >> 6;
    int s  = bs & 63;
    int tid = threadIdx.x;
    int warp = tid >> 5, lane = tid & 31;

    if (tid < ICn) th_s[tid] = d_th[bs * ICn + tid];
    __syncthreads();

    // f[r] for r = warp*8 .. warp*8+7 (8 warps x 8 dots)
    const float4* th4 = (const float4*)th_s;
    float4 a = th4[lane];
#pragma unroll
    for (int d = 0; d < 8; d++) {
        int r = warp * 8 + d;
        float4 p = ((const float4*)(d_ph + (b * Sn + r) * ICn))[lane];
        float acc = a.x * p.x + a.y * p.y + a.z * p.z + a.w * p.w;
#pragma unroll
        for (int o = 16; o; o >>= 1) acc += __shfl_down_sync(0xffffffffu, acc, o);
        if (lane == 0) at_s[r] = acc;
    }
    __syncthreads();

    // softmax over 64 entries by warp 0
    if (warp == 0) {
        float v0 = at_s[lane], v1 = at_s[lane + 32];
        float m = fmaxf(v0, v1);
#pragma unroll
        for (int o = 16; o; o >>= 1) m = fmaxf(m, __shfl_xor_sync(0xffffffffu, m, o));
        float e0 = __expf(v0 - m), e1 = __expf(v1 - m);
        float sum = e0 + e1;
#pragma unroll
        for (int o = 16; o; o >>= 1) sum += __shfl_xor_sync(0xffffffffu, sum, o);
        float inv = 1.0f / sum;
        at_s[lane]      = e0 * inv;
        at_s[lane + 32] = e1 * inv;
    }
    __syncthreads();

    // y[s][i] = sum_r attn[r] * g[r][i] ; threads 0..127 each own an i.
    // Store transposed for the W-projection.
    if (tid < ICn) {
        const float* gb = d_g + b * Sn * ICn + tid;
        float acc = 0.f;
#pragma unroll 16
        for (int r = 0; r < Sn; r++) acc = fmaf(at_s[r], gb[r * ICn], acc);
        d_yT[(b * ICn + tid) * Sn + s] = acc;
    }
}

// ---------------------------------------------------------------------------
// K4: output projection + folded BatchNorm, coalesced via transposed y.
// grid = Bn * (Cn/4) = 256 blocks, 256 threads (4 c x 64 s per block).
// val[(b,c),s] = BN( sum_i W[c][i] * yT[b][i][s] + W_b[c] )
// ---------------------------------------------------------------------------
__global__ void wproj_kernel(const float* __restrict__ W_w,   const float* __restrict__ W_b,
                             const float* __restrict__ gamma, const float* __restrict__ beta,
                             const float* __restrict__ mean,  const float* __restrict__ var) {
    __shared__ float Ws[4 * ICn];        // 4 W rows, 2KB
    int blk = blockIdx.x;
    int b   = blk >> 6;                  // 0..3
    int cg  = blk & 63;                  // 0..63
    int c0  = cg * 4;
    int tid = threadIdx.x;
    int s   = tid & 63;
    int cl  = tid >> 6;                  // 0..3
    int c   = c0 + cl;

    // load 4 W rows (512 floats) coalesced
    Ws[tid]       = W_w[c0 * ICn + tid];
    Ws[tid + 256] = W_w[c0 * ICn + tid + 256];
    __syncthreads();

    const float* yb = d_yT + b * ICn * Sn + s;   // stride Sn per i
    const float* w  = Ws + cl * ICn;
    float acc = 0.f;
#pragma unroll 8
    for (int i = 0; i < ICn; i++)
        acc = fmaf(w[i], yb[i * Sn], acc);

    float inv = gamma[c] * rsqrtf(var[c] + EPSf);
    d_val[(b * Cn + c) * Sn + s] = (acc + W_b[c] - mean[c]) * inv + beta[c];
}

// ---------------------------------------------------------------------------
// K5: broadcast + residual. Pure float4 stream.
// ---------------------------------------------------------------------------
__global__ void residual_kernel(const float* __restrict__ x, float* __restrict__ z) {
    int idx = blockIdx.x * blockDim.x + threadIdx.x;
    float v = d_val[idx >> 8];
    float4 a = ((const float4*)x)[idx];
    a.x += v; a.y += v; a.z += v; a.w += v;
    ((float4*)z)[idx] = a;
}

// ---------------------------------------------------------------------------
extern "C" void kernel_launch(void* const* d_in, const int* in_sizes, int n_in,
                              void* d_out, int out_size) {
    const float* x      = (const float*)d_in[0];
    const float* g_w    = (const float*)d_in[1];
    const float* g_b    = (const float*)d_in[2];
    const float* th_w   = (const float*)d_in[3];
    const float* th_b   = (const float*)d_in[4];
    const float* ph_w   = (const float*)d_in[5];
    const float* ph_b   = (const float*)d_in[6];
    const float* W_w    = (const float*)d_in[7];
    const float* W_b    = (const float*)d_in[8];
    const float* gamma  = (const float*)d_in[9];
    const float* beta   = (const float*)d_in[10];
    const float* mean   = (const float*)d_in[11];
    const float* var    = (const float*)d_in[12];
    float* z = (float*)d_out;

    pool_kernel<<<8192, 256>>>(x);
    dim3 pg(NTOK / 32, 12);
    proj_kernel<<<pg, 256>>>(g_w, g_b, th_w, th_b, ph_w, ph_b);
    attn_kernel<<<NTOK, 256>>>();
    wproj_kernel<<<Bn * (Cn / 4), 256>>>(W_w, W_b, gamma, beta, mean, var);
    residual_kernel<<<(Bn * Cn * Sn * (REGION / 4)) / 256, 256>>>(x, z);
}

// round 6
// speedup vs baseline: 1.5057x; 1.0245x over previous
#include <cuda_runtime.h>

#define Bn 4
#define Cn 256
#define ICn 128
#define Sn 64
#define NTOK (Bn*Sn)        // 256
#define REGION 1024
#define EPSf 1e-5f

// Scratch (allocation-free __device__ globals)
__device__ float d_P   [NTOK*Cn];      // pooled tokens [tok][c]
__device__ float d_g   [NTOK*ICn];
__device__ float d_th  [NTOK*ICn];
__device__ float d_ph  [NTOK*ICn];
__device__ float d_Wt  [ICn*Cn];       // BN-folded W transposed: [i][c]
__device__ float d_bias[Cn];           // BN-folded bias
__device__ float d_val [Bn*Cn*Sn];     // broadcast values [b][c][s]

// ---------------------------------------------------------------------------
// K1: stripe mean pool. One warp per 1024-float contiguous region.
// ---------------------------------------------------------------------------
__global__ void pool_kernel(const float* __restrict__ x) {
    int warp = (blockIdx.x * blockDim.x + threadIdx.x) >> 5;   // 0..65535
    int lane = threadIdx.x & 31;
    const float4* p = (const float4*)(x + (size_t)warp * REGION);
    float sum = 0.f;
#pragma unroll
    for (int i = 0; i < 8; i++) {
        float4 v = p[lane + i * 32];
        sum += (v.x + v.y) + (v.z + v.w);
    }
#pragma unroll
    for (int o = 16; o; o >>= 1) sum += __shfl_down_sync(0xffffffffu, sum, o);
    if (lane == 0) {
        int b   = warp >> 14;
        int rem = warp & 16383;
        int c   = rem >> 6;
        int s   = rem & 63;
        d_P[(b * Sn + s) * Cn + c] = sum * (1.0f / REGION);
    }
}

// ---------------------------------------------------------------------------
// K2: g/theta/phi projections as one tiled GEMM (32x32 tiles).
// blockIdx.y == 12 slice additionally builds the BN-folded transposed W.
// ---------------------------------------------------------------------------
__global__ void proj_kernel(const float* __restrict__ g_w,  const float* __restrict__ g_b,
                            const float* __restrict__ th_w, const float* __restrict__ th_b,
                            const float* __restrict__ ph_w, const float* __restrict__ ph_b,
                            const float* __restrict__ W_w,  const float* __restrict__ W_b,
                            const float* __restrict__ gamma,const float* __restrict__ beta,
                            const float* __restrict__ mean, const float* __restrict__ var) {
    int oT = blockIdx.y;                 // 0..12
    int tid = threadIdx.x;

    if (oT == 12) {
        // BN fold + transpose: 8 blocks x 256 threads, 16 elems each
        int base = blockIdx.x * 4096;
#pragma unroll
        for (int l = 0; l < 16; l++) {
            int idx = base + l * 256 + tid;      // 0..32767 over [c][i]
            int c = idx >> 7, i = idx & 127;
            float inv = gamma[c] * rsqrtf(var[c] + EPSf);
            d_Wt[i * Cn + c] = W_w[idx] * inv;
        }
        if (blockIdx.x == 0) {
            int c = tid;
            float inv = gamma[c] * rsqrtf(var[c] + EPSf);
            d_bias[c] = (W_b[c] - mean[c]) * inv + beta[c];
        }
        return;
    }

    __shared__ float As[32][33];
    __shared__ float Bs[32][33];
    int t0 = blockIdx.x * 32;
    int mat  = oT >> 2;
    int row0 = (oT & 3) * 32;
    const float* wsrc = (mat == 0) ? g_w : (mat == 1) ? th_w : ph_w;
    const float* bsrc = (mat == 0) ? g_b : (mat == 1) ? th_b : ph_b;
    float*       osrc = (mat == 0) ? d_g : (mat == 1) ? d_th : d_ph;

    int tx = tid & 15, ty = tid >> 4;
    float acc[2][2] = {{0.f,0.f},{0.f,0.f}};

    for (int k0 = 0; k0 < Cn; k0 += 32) {
#pragma unroll
        for (int l = 0; l < 4; l++) {
            int idx = tid + l * 256;
            int r = idx >> 5, k = idx & 31;
            As[r][k] = d_P[(t0 + r) * Cn + k0 + k];
            Bs[r][k] = wsrc[(row0 + r) * Cn + k0 + k];
        }
        __syncthreads();
#pragma unroll
        for (int k = 0; k < 32; k++) {
            float a0 = As[ty * 2][k], a1 = As[ty * 2 + 1][k];
            float b0 = Bs[tx * 2][k], b1 = Bs[tx * 2 + 1][k];
            acc[0][0] = fmaf(a0, b0, acc[0][0]);
            acc[0][1] = fmaf(a0, b1, acc[0][1]);
            acc[1][0] = fmaf(a1, b0, acc[1][0]);
            acc[1][1] = fmaf(a1, b1, acc[1][1]);
        }
        __syncthreads();
    }
#pragma unroll
    for (int di = 0; di < 2; di++)
#pragma unroll
        for (int dj = 0; dj < 2; dj++) {
            int tok = t0 + ty * 2 + di;
            int i   = row0 + tx * 2 + dj;
            osrc[tok * ICn + i] = acc[di][dj] + bsrc[i];
        }
}

// ---------------------------------------------------------------------------
// K3: fused attention row + output projection + BN.
// One block per (b,s) token: f = th[s]·ph^T, softmax, y[s] = attn·g (smem),
// then val[b][:][s] = Wt^T · y[s] + bias  (coalesced over c).
// ---------------------------------------------------------------------------
__global__ void attn_kernel() {
    __shared__ float th_s[ICn];          // theta row
    __shared__ float at_s[Sn];           // f row -> attn row
    __shared__ float y_s[ICn];           // y row
    int bs = blockIdx.x;                 // b*Sn + s
    int b  = bs >> 6;
    int s  = bs & 63;
    int tid = threadIdx.x;
    int warp = tid >> 5, lane = tid & 31;

    if (tid < ICn) th_s[tid] = d_th[bs * ICn + tid];
    __syncthreads();

    // f[r] for r = warp*8 .. warp*8+7 (8 warps x 8 dots)
    const float4* th4 = (const float4*)th_s;
    float4 a = th4[lane];
#pragma unroll
    for (int d = 0; d < 8; d++) {
        int r = warp * 8 + d;
        float4 p = ((const float4*)(d_ph + (b * Sn + r) * ICn))[lane];
        float acc = a.x * p.x + a.y * p.y + a.z * p.z + a.w * p.w;
#pragma unroll
        for (int o = 16; o; o >>= 1) acc += __shfl_down_sync(0xffffffffu, acc, o);
        if (lane == 0) at_s[r] = acc;
    }
    __syncthreads();

    // softmax over 64 entries by warp 0
    if (warp == 0) {
        float v0 = at_s[lane], v1 = at_s[lane + 32];
        float m = fmaxf(v0, v1);
#pragma unroll
        for (int o = 16; o; o >>= 1) m = fmaxf(m, __shfl_xor_sync(0xffffffffu, m, o));
        float e0 = __expf(v0 - m), e1 = __expf(v1 - m);
        float sum = e0 + e1;
#pragma unroll
        for (int o = 16; o; o >>= 1) sum += __shfl_xor_sync(0xffffffffu, sum, o);
        float inv = 1.0f / sum;
        at_s[lane]      = e0 * inv;
        at_s[lane + 32] = e1 * inv;
    }
    __syncthreads();

    // y[i] = sum_r attn[r] * g[r][i] ; threads 0..127 each own an i
    if (tid < ICn) {
        const float* gb = d_g + b * Sn * ICn + tid;
        float acc = 0.f;
#pragma unroll 16
        for (int r = 0; r < Sn; r++) acc = fmaf(at_s[r], gb[r * ICn], acc);
        y_s[tid] = acc;
    }
    __syncthreads();

    // val[b][c][s] = sum_i Wt[i][c] * y[i] + bias[c]; thread = c (coalesced)
    {
        const float* wt = d_Wt + tid;    // stride Cn per i
        float acc = 0.f;
#pragma unroll 8
        for (int i = 0; i < ICn; i++)
            acc = fmaf(y_s[i], wt[i * Cn], acc);
        d_val[(b * Cn + tid) * Sn + s] = acc + d_bias[tid];
    }
}

// ---------------------------------------------------------------------------
// K4: broadcast + residual. Pure float4 stream.
// ---------------------------------------------------------------------------
__global__ void residual_kernel(const float* __restrict__ x, float* __restrict__ z) {
    int idx = blockIdx.x * blockDim.x + threadIdx.x;
    float v = d_val[idx >> 8];
    float4 a = ((const float4*)x)[idx];
    a.x += v; a.y += v; a.z += v; a.w += v;
    ((float4*)z)[idx] = a;
}

// ---------------------------------------------------------------------------
extern "C" void kernel_launch(void* const* d_in, const int* in_sizes, int n_in,
                              void* d_out, int out_size) {
    const float* x      = (const float*)d_in[0];
    const float* g_w    = (const float*)d_in[1];
    const float* g_b    = (const float*)d_in[2];
    const float* th_w   = (const float*)d_in[3];
    const float* th_b   = (const float*)d_in[4];
    const float* ph_w   = (const float*)d_in[5];
    const float* ph_b   = (const float*)d_in[6];
    const float* W_w    = (const float*)d_in[7];
    const float* W_b    = (const float*)d_in[8];
    const float* gamma  = (const float*)d_in[9];
    const float* beta   = (const float*)d_in[10];
    const float* mean   = (const float*)d_in[11];
    const float* var    = (const float*)d_in[12];
    float* z = (float*)d_out;

    pool_kernel<<<8192, 256>>>(x);
    dim3 pg(NTOK / 32, 13);
    proj_kernel<<<pg, 256>>>(g_w, g_b, th_w, th_b, ph_w, ph_b,
                             W_w, W_b, gamma, beta, mean, var);
    attn_kernel<<<NTOK, 256>>>();
    residual_kernel<<<(Bn * Cn * Sn * (REGION / 4)) / 256, 256>>>(x, z);
}